// round 14
// baseline (speedup 1.0000x reference)
#include <cuda_runtime.h>
#include <math.h>
#include <cstdint>

// Problem constants (fixed shapes from reference)
#define HW     3136     // 56*56
#define HW4    784      // HW / 4 (float4 chunks per row)
#define B_SZ   64
#define C_IN   512
#define A_DIM  32
#define C_OUT  512
#define BN_EPS 1e-5f
#define POOL_BLOCKS 4096          // 4096 x 8 warps = 32768 rows
#define FC_BLOCKS   (B_SZ * 2)    // one per (batch, {channel|filter})

// Scratch for pooled means: [B, C_in]
__device__ float g_pooled[B_SZ * C_IN];
// Per-batch arrival counters. Protocol (mod 1024, replay-safe):
//   512 pool warps add 1 each (release)  -> bit9 becomes set
//   2 fc blocks add 256 each after pass  -> bit9 cleared for next replay
__device__ unsigned int g_cnt[B_SZ];

__device__ __forceinline__ void red_release_add(unsigned int* p, unsigned int v) {
    asm volatile("red.release.gpu.global.add.u32 [%0], %1;"
                 :: "l"(p), "r"(v) : "memory");
}
__device__ __forceinline__ void red_relaxed_add(unsigned int* p, unsigned int v) {
    asm volatile("red.relaxed.gpu.global.add.u32 [%0], %1;"
                 :: "l"(p), "r"(v) : "memory");
}
__device__ __forceinline__ unsigned int ld_acquire(const unsigned int* p) {
    unsigned int v;
    asm volatile("ld.acquire.gpu.global.u32 %0, [%1];"
                 : "=r"(v) : "l"(p) : "memory");
    return v;
}

// ---------------------------------------------------------------------------
// Fused kernel. Grid = 4224 blocks x 256 threads.
//  Blocks [0, 4096): pool — EXACT R7 streaming loop; each warp's lane0
//    publishes its row with ONE red.release (no threadfence -> no CCTL.IVALL,
//    no extra syncthreads). This is the fix for the R4/R8 bandwidth collapse.
//  Blocks [4096, 4224): fc — dispatched last (in-order bid dispatch), they
//    land in the final partial wave. Block (b,t): acquire-spin on g_cnt[b],
//    then h = relu(BN(pooled @ fc_w^T)), then 512 sigmoid dots with
//    coalesced weight loads + intra-group-of-8 shuffle reduction.
// ---------------------------------------------------------------------------
__global__ void fused_kernel(
    const float* __restrict__ x,
    const float* __restrict__ fc_w,         // [A, C_in]
    const float* __restrict__ bn_gamma,     // [A]
    const float* __restrict__ bn_beta,      // [A]
    const float* __restrict__ bn_mean,      // [A]
    const float* __restrict__ bn_var,       // [A]
    const float* __restrict__ channel_fc_w, // [C_in, A]
    const float* __restrict__ channel_fc_b, // [C_in]
    const float* __restrict__ filter_fc_w,  // [C_out, A]
    const float* __restrict__ filter_fc_b,  // [C_out]
    float* __restrict__ out)                // [2 * B * 512]
{
    const int tid  = threadIdx.x;
    const int warp = tid >> 5;
    const int lane = tid & 31;

    if (blockIdx.x < POOL_BLOCKS) {
        // ================= POOL PATH (unchanged R7 streaming) =================
        const int gwarp = blockIdx.x * 8 + warp;        // row = (b, c)
        const int b     = blockIdx.x >> 6;
        const float4* __restrict__ row =
            reinterpret_cast<const float4*>(x + (size_t)gwarp * HW);

        float s0 = 0.f, s1 = 0.f;
        int i = lane;
        #pragma unroll 4
        for (; i + 32 < HW4; i += 64) {
            float4 v0 = __ldg(&row[i]);
            float4 v1 = __ldg(&row[i + 32]);
            s0 += (v0.x + v0.y) + (v0.z + v0.w);
            s1 += (v1.x + v1.y) + (v1.z + v1.w);
        }
        if (i < HW4) {
            float4 v0 = __ldg(&row[i]);
            s0 += (v0.x + v0.y) + (v0.z + v0.w);
        }
        float s = s0 + s1;
        #pragma unroll
        for (int off = 16; off > 0; off >>= 1)
            s += __shfl_xor_sync(0xFFFFFFFFu, s, off);

        if (lane == 0) {
            g_pooled[gwarp] = s * (1.0f / (float)HW);
            red_release_add(&g_cnt[b], 1u);   // release MY row write
        }
        return;
    }

    // ===================== FC PATH (128 trailing blocks) =====================
    const int idx = blockIdx.x - POOL_BLOCKS;
    const int b   = idx >> 1;
    const int t   = idx & 1;                 // 0 = channel, 1 = filter

    const float* __restrict__ w_mat  = t ? filter_fc_w : channel_fc_w;
    const float* __restrict__ w_bias = t ? filter_fc_b : channel_fc_b;

    __shared__ __align__(16) float s_pooled[C_IN];
    __shared__ __align__(16) float s_h[A_DIM];

    // acquire-spin until this batch's 512 pool warps have arrived (bit9 set)
    if (tid == 0) {
        while (!(ld_acquire(&g_cnt[b]) & 512u))
            __nanosleep(64);
        red_relaxed_add(&g_cnt[b], 256u);    // my half of the replay reset
    }
    __syncthreads();

    // stage pooled row (L2; bypass L1 for safety)
    s_pooled[tid]       = __ldcg(&g_pooled[b * C_IN + tid]);
    s_pooled[tid + 256] = __ldcg(&g_pooled[b * C_IN + tid + 256]);
    __syncthreads();

    // ---- h: warp w computes a = w + 8k, k = 0..3 (warp-parallel dots) ----
    const float4* __restrict__ sp4 = reinterpret_cast<const float4*>(s_pooled);
    #pragma unroll
    for (int k = 0; k < 4; ++k) {
        const int a = warp + k * 8;
        const float4* __restrict__ w4 =
            reinterpret_cast<const float4*>(fc_w + a * C_IN);
        float acc = 0.f;
        #pragma unroll
        for (int j = 0; j < 4; ++j) {
            float4 wv = __ldg(&w4[lane + 32 * j]);   // coalesced (4 lines)
            float4 pv = sp4[lane + 32 * j];
            acc = fmaf(wv.x, pv.x, acc);
            acc = fmaf(wv.y, pv.y, acc);
            acc = fmaf(wv.z, pv.z, acc);
            acc = fmaf(wv.w, pv.w, acc);
        }
        #pragma unroll
        for (int off = 16; off > 0; off >>= 1)
            acc += __shfl_xor_sync(0xFFFFFFFFu, acc, off);
        if (lane == 0) {
            float inv_std = rsqrtf(__ldg(&bn_var[a]) + BN_EPS);
            float hv = (acc - __ldg(&bn_mean[a])) *
                       (__ldg(&bn_gamma[a]) * inv_std) + __ldg(&bn_beta[a]);
            s_h[a] = fmaxf(hv, 0.f);
        }
    }
    __syncthreads();

    // ---- output: 512 dots, coalesced weight loads + group-of-8 shuffle ----
    // Warp w covers c in [w*64, w*64+64) as two 32-row ranges. Per iter j:
    // lane loads W[row][acol..acol+3] where row = c0 + 4j + (lane>>3),
    // acol = (lane&7)*4 — the warp-LDG spans exactly 4 rows x 128B = 4 lines
    // (fully coalesced). Butterfly over lane groups of 8 completes each dot.
    const float4* __restrict__ w4 = reinterpret_cast<const float4*>(w_mat);
    #pragma unroll
    for (int r = 0; r < 2; ++r) {
        const int c0 = warp * 64 + r * 32;
        #pragma unroll
        for (int j = 0; j < 8; ++j) {
            const int row  = c0 + j * 4 + (lane >> 3);
            const int asub = (lane & 7) * 4;
            float4 wv = __ldg(&w4[row * 8 + (lane & 7)]);
            float p = s_h[asub + 0] * wv.x + s_h[asub + 1] * wv.y +
                      s_h[asub + 2] * wv.z + s_h[asub + 3] * wv.w;
            p += __shfl_xor_sync(0xFFFFFFFFu, p, 1);
            p += __shfl_xor_sync(0xFFFFFFFFu, p, 2);
            p += __shfl_xor_sync(0xFFFFFFFFu, p, 4);
            if ((lane & 7) == 0) {
                const float acc = p + __ldg(&w_bias[row]);
                out[(size_t)t * (B_SZ * C_IN) + b * C_IN + row] =
                    __fdividef(1.0f, 1.0f + __expf(-acc));
            }
        }
    }
}

extern "C" void kernel_launch(void* const* d_in, const int* in_sizes, int n_in,
                              void* d_out, int out_size) {
    const float* x            = (const float*)d_in[0];
    const float* fc_w         = (const float*)d_in[1];
    const float* bn_gamma     = (const float*)d_in[2];
    const float* bn_beta      = (const float*)d_in[3];
    const float* bn_mean      = (const float*)d_in[4];
    const float* bn_var       = (const float*)d_in[5];
    const float* channel_fc_w = (const float*)d_in[6];
    const float* channel_fc_b = (const float*)d_in[7];
    const float* filter_fc_w  = (const float*)d_in[8];
    const float* filter_fc_b  = (const float*)d_in[9];
    float* out = (float*)d_out;

    fused_kernel<<<POOL_BLOCKS + FC_BLOCKS, 256>>>(
        x, fc_w, bn_gamma, bn_beta, bn_mean, bn_var,
        channel_fc_w, channel_fc_b, filter_fc_w, filter_fc_b, out);
}

// round 15
// speedup vs baseline: 1.1081x; 1.1081x over previous
#include <cuda_runtime.h>
#include <math.h>
#include <cstdint>

// Problem constants (fixed shapes from reference)
#define HW     3136     // 56*56
#define HW4    784      // HW / 4 (float4 chunks per row)
#define B_SZ   64
#define C_IN   512
#define A_DIM  32
#define C_OUT  512
#define BN_EPS 1e-5f

// fc smem layout (floats):
//   s_lin    : 16384  raw attention tile (cp.async dest)
//   s_wT     : 32*513 transposed attention tile
//   s_pooled : 512
//   s_bias   : 512
//   s_bn     : 128  [gamma | beta | mean | var] x 32
//   s_h      : 32
#define SWT_STRIDE 513
#define SMEM_FLOATS (16384 + A_DIM * SWT_STRIDE + C_IN + C_IN + 128 + A_DIM)

// Scratch for pooled means: [B, C_in]
__device__ float g_pooled[B_SZ * C_IN];

__device__ __forceinline__ void cp_async16(uint32_t dst_smem, const void* src) {
    asm volatile("cp.async.cg.shared.global [%0], [%1], 16;"
                 :: "r"(dst_smem), "l"(src));
}

// ---------------------------------------------------------------------------
// Kernel 1: global average pool — R7 minimal streaming form, with ONE
// change: __ldcs (evict-first) on the x reads. x is 411MB read-once;
// default policy churns L2 allocating lines that will never be re-read.
// Fusion is permanently abandoned: three designs (R4/R8/R14) all lost
// 17-28% streaming BW vs this standalone loop.
// ---------------------------------------------------------------------------
__global__ __launch_bounds__(256) void pool_kernel(const float* __restrict__ x) {
    const int gwarp = (blockIdx.x * blockDim.x + threadIdx.x) >> 5;
    const int lane  = threadIdx.x & 31;
    if (gwarp >= B_SZ * C_IN) return;

    const float4* __restrict__ row =
        reinterpret_cast<const float4*>(x + (size_t)gwarp * HW);

    float s0 = 0.f, s1 = 0.f;
    int i = lane;
    #pragma unroll 4
    for (; i + 32 < HW4; i += 64) {
        float4 v0 = __ldcs(&row[i]);        // streaming: evict-first
        float4 v1 = __ldcs(&row[i + 32]);
        s0 += (v0.x + v0.y) + (v0.z + v0.w);
        s1 += (v1.x + v1.y) + (v1.z + v1.w);
    }
    if (i < HW4) {
        float4 v0 = __ldcs(&row[i]);
        s0 += (v0.x + v0.y) + (v0.z + v0.w);
    }
    float s = s0 + s1;

    #pragma unroll
    for (int off = 16; off > 0; off >>= 1)
        s += __shfl_xor_sync(0xFFFFFFFFu, s, off);

    if (lane == 0)
        g_pooled[gwarp] = s * (1.0f / (float)HW);
}

// ---------------------------------------------------------------------------
// Kernel 2: FC chain (R12 cp.async version — best measured fc).
// Grid = 128 blocks: block (b, t). 512 threads, one output per thread.
// ---------------------------------------------------------------------------
__global__ __launch_bounds__(512) void fc_kernel(
    const float* __restrict__ fc_w,         // [A, C_in]
    const float* __restrict__ bn_gamma,     // [A]
    const float* __restrict__ bn_beta,      // [A]
    const float* __restrict__ bn_mean,      // [A]
    const float* __restrict__ bn_var,       // [A]
    const float* __restrict__ channel_fc_w, // [C_in, A]
    const float* __restrict__ channel_fc_b, // [C_in]
    const float* __restrict__ filter_fc_w,  // [C_out, A]
    const float* __restrict__ filter_fc_b,  // [C_out]
    float* __restrict__ out)                // [2 * B * 512]
{
    extern __shared__ __align__(16) float smem[];
    float* s_lin    = smem;                           // 16384
    float* s_wT     = smem + 16384;                   // 32*513
    float* s_pooled = s_wT + A_DIM * SWT_STRIDE;      // 512
    float* s_bias   = s_pooled + C_IN;                // 512
    float* s_bn     = s_bias + C_IN;                  // 128
    float* s_h      = s_bn + 128;                     // 32

    const int b    = blockIdx.x >> 1;
    const int t    = blockIdx.x & 1;        // 0 = channel, 1 = filter
    const int tid  = threadIdx.x;
    const int warp = tid >> 5;
    const int lane = tid & 31;

    const float* __restrict__ w_mat  = t ? filter_fc_w : channel_fc_w;
    const float* __restrict__ w_bias = t ? filter_fc_b : channel_fc_b;

    // ---- fc_w rows for this warp's two h-dots: register loads, hoisted ----
    const int a0 = warp, a1 = warp + 16;
    const float4* __restrict__ f0 =
        reinterpret_cast<const float4*>(fc_w + a0 * C_IN);
    const float4* __restrict__ f1 =
        reinterpret_cast<const float4*>(fc_w + a1 * C_IN);
    float4 fw00 = __ldg(&f0[lane]);      float4 fw01 = __ldg(&f0[lane + 32]);
    float4 fw02 = __ldg(&f0[lane + 64]); float4 fw03 = __ldg(&f0[lane + 96]);
    float4 fw10 = __ldg(&f1[lane]);      float4 fw11 = __ldg(&f1[lane + 32]);
    float4 fw12 = __ldg(&f1[lane + 64]); float4 fw13 = __ldg(&f1[lane + 96]);

    // ---- cp.async staging: tile + pooled + bias + bn, all in flight ----
    const uint32_t s_lin_a    = (uint32_t)__cvta_generic_to_shared(s_lin);
    const uint32_t s_pooled_a = (uint32_t)__cvta_generic_to_shared(s_pooled);
    const uint32_t s_bias_a   = (uint32_t)__cvta_generic_to_shared(s_bias);
    const uint32_t s_bn_a     = (uint32_t)__cvta_generic_to_shared(s_bn);

    #pragma unroll
    for (int k = 0; k < 8; ++k) {
        const int i = tid + k * 512;              // float4 index
        cp_async16(s_lin_a + i * 16, w_mat + i * 4);
    }
    if (tid < 128) {
        cp_async16(s_pooled_a + tid * 16, g_pooled + b * C_IN + tid * 4);
    } else if (tid < 256) {
        const int j = tid - 128;
        cp_async16(s_bias_a + j * 16, w_bias + j * 4);
    } else if (tid < 264) {
        const int j = tid - 256;
        cp_async16(s_bn_a + j * 16, bn_gamma + j * 4);          // [0,32)
    } else if (tid < 272) {
        const int j = tid - 264;
        cp_async16(s_bn_a + 128 + j * 16, bn_beta + j * 4);     // [32,64)
    } else if (tid < 280) {
        const int j = tid - 272;
        cp_async16(s_bn_a + 256 + j * 16, bn_mean + j * 4);     // [64,96)
    } else if (tid < 288) {
        const int j = tid - 280;
        cp_async16(s_bn_a + 384 + j * 16, bn_var + j * 4);      // [96,128)
    }
    asm volatile("cp.async.commit_group;");
    asm volatile("cp.async.wait_group 0;");
    __syncthreads();

    // ---- transpose s_lin -> s_wT (both sides conflict-free) ----
    #pragma unroll
    for (int k = 0; k < 8; ++k) {
        const int i = tid + k * 512;
        float4 v = *reinterpret_cast<const float4*>(s_lin + i * 4);
        const int f = i << 2;
        const int c = f >> 5;                // output row (0..511)
        const int a = f & 31;                // a-offset (multiple of 4)
        s_wT[(a + 0) * SWT_STRIDE + c] = v.x;
        s_wT[(a + 1) * SWT_STRIDE + c] = v.y;
        s_wT[(a + 2) * SWT_STRIDE + c] = v.z;
        s_wT[(a + 3) * SWT_STRIDE + c] = v.w;
    }

    // ---- h: warp-parallel dots (fc_w in regs, pooled in smem) ----
    const float4* __restrict__ sp4 = reinterpret_cast<const float4*>(s_pooled);
    float4 pv0 = sp4[lane];      float4 pv1 = sp4[lane + 32];
    float4 pv2 = sp4[lane + 64]; float4 pv3 = sp4[lane + 96];

    float acc0 = 0.f, acc1 = 0.f;
    acc0 = fmaf(fw00.x, pv0.x, acc0); acc0 = fmaf(fw00.y, pv0.y, acc0);
    acc0 = fmaf(fw00.z, pv0.z, acc0); acc0 = fmaf(fw00.w, pv0.w, acc0);
    acc0 = fmaf(fw01.x, pv1.x, acc0); acc0 = fmaf(fw01.y, pv1.y, acc0);
    acc0 = fmaf(fw01.z, pv1.z, acc0); acc0 = fmaf(fw01.w, pv1.w, acc0);
    acc0 = fmaf(fw02.x, pv2.x, acc0); acc0 = fmaf(fw02.y, pv2.y, acc0);
    acc0 = fmaf(fw02.z, pv2.z, acc0); acc0 = fmaf(fw02.w, pv2.w, acc0);
    acc0 = fmaf(fw03.x, pv3.x, acc0); acc0 = fmaf(fw03.y, pv3.y, acc0);
    acc0 = fmaf(fw03.z, pv3.z, acc0); acc0 = fmaf(fw03.w, pv3.w, acc0);

    acc1 = fmaf(fw10.x, pv0.x, acc1); acc1 = fmaf(fw10.y, pv0.y, acc1);
    acc1 = fmaf(fw10.z, pv0.z, acc1); acc1 = fmaf(fw10.w, pv0.w, acc1);
    acc1 = fmaf(fw11.x, pv1.x, acc1); acc1 = fmaf(fw11.y, pv1.y, acc1);
    acc1 = fmaf(fw11.z, pv1.z, acc1); acc1 = fmaf(fw11.w, pv1.w, acc1);
    acc1 = fmaf(fw12.x, pv2.x, acc1); acc1 = fmaf(fw12.y, pv2.y, acc1);
    acc1 = fmaf(fw12.z, pv2.z, acc1); acc1 = fmaf(fw12.w, pv2.w, acc1);
    acc1 = fmaf(fw13.x, pv3.x, acc1); acc1 = fmaf(fw13.y, pv3.y, acc1);
    acc1 = fmaf(fw13.z, pv3.z, acc1); acc1 = fmaf(fw13.w, pv3.w, acc1);

    #pragma unroll
    for (int off = 16; off > 0; off >>= 1) {
        acc0 += __shfl_xor_sync(0xFFFFFFFFu, acc0, off);
        acc1 += __shfl_xor_sync(0xFFFFFFFFu, acc1, off);
    }
    if (lane == 0) {
        float h0 = (acc0 - s_bn[64 + a0]) *
                   (s_bn[a0] * rsqrtf(s_bn[96 + a0] + BN_EPS)) + s_bn[32 + a0];
        float h1 = (acc1 - s_bn[64 + a1]) *
                   (s_bn[a1] * rsqrtf(s_bn[96 + a1] + BN_EPS)) + s_bn[32 + a1];
        s_h[a0] = fmaxf(h0, 0.f);
        s_h[a1] = fmaxf(h1, 0.f);
    }
    __syncthreads();

    // ---- attention output: dot over smem-transposed weights ----
    float acc = s_bias[tid];
    #pragma unroll
    for (int a = 0; a < A_DIM; ++a)
        acc = fmaf(s_h[a], s_wT[a * SWT_STRIDE + tid], acc);

    // fast sigmoid (MUFU.EX2 + fast rcp): rel err ~1e-7, budget 1e-3
    out[(size_t)t * (B_SZ * C_IN) + b * C_IN + tid] =
        __fdividef(1.0f, 1.0f + __expf(-acc));
}

extern "C" void kernel_launch(void* const* d_in, const int* in_sizes, int n_in,
                              void* d_out, int out_size) {
    const float* x            = (const float*)d_in[0];
    const float* fc_w         = (const float*)d_in[1];
    const float* bn_gamma     = (const float*)d_in[2];
    const float* bn_beta      = (const float*)d_in[3];
    const float* bn_mean      = (const float*)d_in[4];
    const float* bn_var       = (const float*)d_in[5];
    const float* channel_fc_w = (const float*)d_in[6];
    const float* channel_fc_b = (const float*)d_in[7];
    const float* filter_fc_w  = (const float*)d_in[8];
    const float* filter_fc_b  = (const float*)d_in[9];
    float* out = (float*)d_out;

    const int smem_bytes = SMEM_FLOATS * (int)sizeof(float);
    static bool attr_set = false;   // host-side only; idempotent runtime attr
    if (!attr_set) {
        cudaFuncSetAttribute(fc_kernel,
                             cudaFuncAttributeMaxDynamicSharedMemorySize,
                             smem_bytes);
        attr_set = true;
    }

    pool_kernel<<<(B_SZ * C_IN) / 8, 256>>>(x);

    fc_kernel<<<B_SZ * 2, 512, smem_bytes>>>(
        fc_w, bn_gamma, bn_beta, bn_mean, bn_var,
        channel_fc_w, channel_fc_b, filter_fc_w, filter_fc_b, out);
}

// round 16
// speedup vs baseline: 1.1446x; 1.0329x over previous
#include <cuda_runtime.h>
#include <math.h>
#include <cstdint>

// Problem constants (fixed shapes from reference)
#define HW     3136     // 56*56
#define HW4    784      // HW / 4 (float4 chunks per row)
#define B_SZ   64
#define C_IN   512
#define A_DIM  32
#define C_OUT  512
#define BN_EPS 1e-5f

// fc smem layout (floats):
//   s_lin    : 512 rows x 36 words (32 data + 4 pad) = 18432 floats.
//              Padded row-major weight tile. Stride 36 (~=4 mod 32) makes
//              per-thread LDS.128 row reads bank-conflict-free: each 8-lane
//              phase spans banks (4c+const)..+3, tiling all 32 banks.
//   s_pooled : 512
//   s_bias   : 512
//   s_bn     : 128  [gamma | beta | mean | var] x 32
//   s_h      : 32
#define ROW_STRIDE_W 36     // words per padded row
#define S_LIN_FLOATS (C_IN * ROW_STRIDE_W)
#define SMEM_FLOATS  (S_LIN_FLOATS + C_IN + C_IN + 128 + A_DIM)

// Scratch for pooled means: [B, C_in]
__device__ float g_pooled[B_SZ * C_IN];

__device__ __forceinline__ void cp_async16(uint32_t dst_smem, const void* src) {
    asm volatile("cp.async.cg.shared.global [%0], [%1], 16;"
                 :: "r"(dst_smem), "l"(src));
}

// ---------------------------------------------------------------------------
// Kernel 1: global average pool — UNCHANGED from R15 (best measured config:
// minimal streaming loop, 2-wide MLP, __ldcs evict-first). ~59us @ 7.1TB/s.
// Fusion / PDL / prefetch additions all measured as regressions; keep clean.
// ---------------------------------------------------------------------------
__global__ __launch_bounds__(256) void pool_kernel(const float* __restrict__ x) {
    const int gwarp = (blockIdx.x * blockDim.x + threadIdx.x) >> 5;
    const int lane  = threadIdx.x & 31;
    if (gwarp >= B_SZ * C_IN) return;

    const float4* __restrict__ row =
        reinterpret_cast<const float4*>(x + (size_t)gwarp * HW);

    float s0 = 0.f, s1 = 0.f;
    int i = lane;
    #pragma unroll 4
    for (; i + 32 < HW4; i += 64) {
        float4 v0 = __ldcs(&row[i]);        // streaming: evict-first
        float4 v1 = __ldcs(&row[i + 32]);
        s0 += (v0.x + v0.y) + (v0.z + v0.w);
        s1 += (v1.x + v1.y) + (v1.z + v1.w);
    }
    if (i < HW4) {
        float4 v0 = __ldcs(&row[i]);
        s0 += (v0.x + v0.y) + (v0.z + v0.w);
    }
    float s = s0 + s1;

    #pragma unroll
    for (int off = 16; off > 0; off >>= 1)
        s += __shfl_xor_sync(0xFFFFFFFFu, s, off);

    if (lane == 0)
        g_pooled[gwarp] = s * (1.0f / (float)HW);
}

// ---------------------------------------------------------------------------
// Kernel 2: FC chain. Grid = 128 blocks: block (b, t). 512 threads.
// cp.async stages the weight tile DIRECTLY into the padded conflict-free
// layout — no smem->smem transpose (saves ~1000cyc of crossbar traffic on
// the post-wait critical path vs the R12/R15 version).
// ---------------------------------------------------------------------------
__global__ __launch_bounds__(512) void fc_kernel(
    const float* __restrict__ fc_w,         // [A, C_in]
    const float* __restrict__ bn_gamma,     // [A]
    const float* __restrict__ bn_beta,      // [A]
    const float* __restrict__ bn_mean,      // [A]
    const float* __restrict__ bn_var,       // [A]
    const float* __restrict__ channel_fc_w, // [C_in, A]
    const float* __restrict__ channel_fc_b, // [C_in]
    const float* __restrict__ filter_fc_w,  // [C_out, A]
    const float* __restrict__ filter_fc_b,  // [C_out]
    float* __restrict__ out)                // [2 * B * 512]
{
    extern __shared__ __align__(16) float smem[];
    float* s_lin    = smem;                           // 512 x 36
    float* s_pooled = smem + S_LIN_FLOATS;            // 512 (16B-aligned)
    float* s_bias   = s_pooled + C_IN;                // 512
    float* s_bn     = s_bias + C_IN;                  // 128
    float* s_h      = s_bn + 128;                     // 32

    const int b    = blockIdx.x >> 1;
    const int t    = blockIdx.x & 1;        // 0 = channel, 1 = filter
    const int tid  = threadIdx.x;
    const int warp = tid >> 5;
    const int lane = tid & 31;

    const float* __restrict__ w_mat  = t ? filter_fc_w : channel_fc_w;
    const float* __restrict__ w_bias = t ? filter_fc_b : channel_fc_b;

    // ---- fc_w rows for this warp's two h-dots: register loads, hoisted ----
    const int a0 = warp, a1 = warp + 16;
    const float4* __restrict__ f0 =
        reinterpret_cast<const float4*>(fc_w + a0 * C_IN);
    const float4* __restrict__ f1 =
        reinterpret_cast<const float4*>(fc_w + a1 * C_IN);
    float4 fw00 = __ldg(&f0[lane]);      float4 fw01 = __ldg(&f0[lane + 32]);
    float4 fw02 = __ldg(&f0[lane + 64]); float4 fw03 = __ldg(&f0[lane + 96]);
    float4 fw10 = __ldg(&f1[lane]);      float4 fw11 = __ldg(&f1[lane + 32]);
    float4 fw12 = __ldg(&f1[lane + 64]); float4 fw13 = __ldg(&f1[lane + 96]);

    // ---- cp.async staging: tile (padded layout) + pooled + bias + bn ----
    const uint32_t s_lin_a    = (uint32_t)__cvta_generic_to_shared(s_lin);
    const uint32_t s_pooled_a = (uint32_t)__cvta_generic_to_shared(s_pooled);
    const uint32_t s_bias_a   = (uint32_t)__cvta_generic_to_shared(s_bias);
    const uint32_t s_bn_a     = (uint32_t)__cvta_generic_to_shared(s_bn);

    #pragma unroll
    for (int k = 0; k < 8; ++k) {
        const int i    = tid + k * 512;      // global float4 index (0..4095)
        const int row  = i >> 3;             // weight row (8 chunks per row)
        const int chnk = i & 7;              // 16B chunk within row
        cp_async16(s_lin_a + (row * ROW_STRIDE_W + chnk * 4) * 4,
                   w_mat + i * 4);
    }
    if (tid < 128) {
        cp_async16(s_pooled_a + tid * 16, g_pooled + b * C_IN + tid * 4);
    } else if (tid < 256) {
        const int j = tid - 128;
        cp_async16(s_bias_a + j * 16, w_bias + j * 4);
    } else if (tid < 264) {
        const int j = tid - 256;
        cp_async16(s_bn_a + j * 16, bn_gamma + j * 4);          // [0,32)
    } else if (tid < 272) {
        const int j = tid - 264;
        cp_async16(s_bn_a + 128 + j * 16, bn_beta + j * 4);     // [32,64)
    } else if (tid < 280) {
        const int j = tid - 272;
        cp_async16(s_bn_a + 256 + j * 16, bn_mean + j * 4);     // [64,96)
    } else if (tid < 288) {
        const int j = tid - 280;
        cp_async16(s_bn_a + 384 + j * 16, bn_var + j * 4);      // [96,128)
    }
    asm volatile("cp.async.commit_group;");
    asm volatile("cp.async.wait_group 0;");
    __syncthreads();

    // ---- h: warp-parallel dots (fc_w in regs, pooled in smem) ----
    const float4* __restrict__ sp4 = reinterpret_cast<const float4*>(s_pooled);
    float4 pv0 = sp4[lane];      float4 pv1 = sp4[lane + 32];
    float4 pv2 = sp4[lane + 64]; float4 pv3 = sp4[lane + 96];

    float acc0 = 0.f, acc1 = 0.f;
    acc0 = fmaf(fw00.x, pv0.x, acc0); acc0 = fmaf(fw00.y, pv0.y, acc0);
    acc0 = fmaf(fw00.z, pv0.z, acc0); acc0 = fmaf(fw00.w, pv0.w, acc0);
    acc0 = fmaf(fw01.x, pv1.x, acc0); acc0 = fmaf(fw01.y, pv1.y, acc0);
    acc0 = fmaf(fw01.z, pv1.z, acc0); acc0 = fmaf(fw01.w, pv1.w, acc0);
    acc0 = fmaf(fw02.x, pv2.x, acc0); acc0 = fmaf(fw02.y, pv2.y, acc0);
    acc0 = fmaf(fw02.z, pv2.z, acc0); acc0 = fmaf(fw02.w, pv2.w, acc0);
    acc0 = fmaf(fw03.x, pv3.x, acc0); acc0 = fmaf(fw03.y, pv3.y, acc0);
    acc0 = fmaf(fw03.z, pv3.z, acc0); acc0 = fmaf(fw03.w, pv3.w, acc0);

    acc1 = fmaf(fw10.x, pv0.x, acc1); acc1 = fmaf(fw10.y, pv0.y, acc1);
    acc1 = fmaf(fw10.z, pv0.z, acc1); acc1 = fmaf(fw10.w, pv0.w, acc1);
    acc1 = fmaf(fw11.x, pv1.x, acc1); acc1 = fmaf(fw11.y, pv1.y, acc1);
    acc1 = fmaf(fw11.z, pv1.z, acc1); acc1 = fmaf(fw11.w, pv1.w, acc1);
    acc1 = fmaf(fw12.x, pv2.x, acc1); acc1 = fmaf(fw12.y, pv2.y, acc1);
    acc1 = fmaf(fw12.z, pv2.z, acc1); acc1 = fmaf(fw12.w, pv2.w, acc1);
    acc1 = fmaf(fw13.x, pv3.x, acc1); acc1 = fmaf(fw13.y, pv3.y, acc1);
    acc1 = fmaf(fw13.z, pv3.z, acc1); acc1 = fmaf(fw13.w, pv3.w, acc1);

    #pragma unroll
    for (int off = 16; off > 0; off >>= 1) {
        acc0 += __shfl_xor_sync(0xFFFFFFFFu, acc0, off);
        acc1 += __shfl_xor_sync(0xFFFFFFFFu, acc1, off);
    }
    if (lane == 0) {
        float h0 = (acc0 - s_bn[64 + a0]) *
                   (s_bn[a0] * rsqrtf(s_bn[96 + a0] + BN_EPS)) + s_bn[32 + a0];
        float h1 = (acc1 - s_bn[64 + a1]) *
                   (s_bn[a1] * rsqrtf(s_bn[96 + a1] + BN_EPS)) + s_bn[32 + a1];
        s_h[a0] = fmaxf(h0, 0.f);
        s_h[a1] = fmaxf(h1, 0.f);
    }
    __syncthreads();

    // ---- attention output: thread c reads its padded weight row via 8
    //      conflict-free LDS.128 (row stride 9 float4) and dots with s_h ----
    const float4* __restrict__ sl4 = reinterpret_cast<const float4*>(s_lin);
    float acc = s_bias[tid];
    #pragma unroll
    for (int j = 0; j < 8; ++j) {
        float4 wv = sl4[tid * (ROW_STRIDE_W / 4) + j];
        acc = fmaf(s_h[4 * j + 0], wv.x, acc);
        acc = fmaf(s_h[4 * j + 1], wv.y, acc);
        acc = fmaf(s_h[4 * j + 2], wv.z, acc);
        acc = fmaf(s_h[4 * j + 3], wv.w, acc);
    }

    // fast sigmoid (MUFU.EX2 + fast rcp): rel err ~1e-7, budget 1e-3
    out[(size_t)t * (B_SZ * C_IN) + b * C_IN + tid] =
        __fdividef(1.0f, 1.0f + __expf(-acc));
}

extern "C" void kernel_launch(void* const* d_in, const int* in_sizes, int n_in,
                              void* d_out, int out_size) {
    const float* x            = (const float*)d_in[0];
    const float* fc_w         = (const float*)d_in[1];
    const float* bn_gamma     = (const float*)d_in[2];
    const float* bn_beta      = (const float*)d_in[3];
    const float* bn_mean     = (const float*)d_in[4];
    const float* bn_var       = (const float*)d_in[5];
    const float* channel_fc_w = (const float*)d_in[6];
    const float* channel_fc_b = (const float*)d_in[7];
    const float* filter_fc_w  = (const float*)d_in[8];
    const float* filter_fc_b  = (const float*)d_in[9];
    float* out = (float*)d_out;

    const int smem_bytes = SMEM_FLOATS * (int)sizeof(float);
    static bool attr_set = false;   // host-side only; idempotent runtime attr
    if (!attr_set) {
        cudaFuncSetAttribute(fc_kernel,
                             cudaFuncAttributeMaxDynamicSharedMemorySize,
                             smem_bytes);
        attr_set = true;
    }

    pool_kernel<<<(B_SZ * C_IN) / 8, 256>>>(x);

    fc_kernel<<<B_SZ * 2, 512, smem_bytes>>>(
        fc_w, bn_gamma, bn_beta, bn_mean, bn_var,
        channel_fc_w, channel_fc_b, filter_fc_w, filter_fc_b, out);
}